// round 8
// baseline (speedup 1.0000x reference)
#include <cuda_runtime.h>
#include <cuda_bf16.h>
#include <cstdint>
#include <math.h>

#define BATCH 16
#define DIMC 256
#define HH 56
#define WW 56
#define HEADS 8
#define DH 32
#define HW 3136
#define H28 28
#define S28 784
#define HP 14
#define SP 196
#define SCAL 0.17677669529663687f

// ---------------- scratch ----------------
__device__ float g_q    [BATCH * DIMC * HW];
__device__ float g_p28a [BATCH * DIMC * S28];
__device__ float g_p28b [BATCH * DIMC * S28];
__device__ float g_p14  [BATCH * DIMC * SP];
__device__ float g_kv   [BATCH * 2 * DIMC * SP];
__device__ float g_gf   [BATCH * DIMC * HW];
__device__ float g_mixin[BATCH * DIMC * HW];

// ================= helpers =================
__device__ __forceinline__ uint32_t smem_u32(const void* p) {
    uint32_t a;
    asm("{ .reg .u64 t; cvta.to.shared.u64 t, %1; cvt.u32.u64 %0, t; }" : "=r"(a) : "l"(p));
    return a;
}

#define LDSM_X4(r0, r1, r2, r3, addr) \
    asm volatile("ldmatrix.sync.aligned.m8n8.x4.shared.b16 {%0,%1,%2,%3}, [%4];" \
        : "=r"(r0), "=r"(r1), "=r"(r2), "=r"(r3) : "r"(addr))

__device__ __forceinline__ void mma_bf16(float* d, const uint32_t* a, const uint32_t* b) {
    asm volatile(
        "mma.sync.aligned.m16n8k16.row.col.f32.bf16.bf16.f32 "
        "{%0,%1,%2,%3}, {%4,%5,%6,%7}, {%8,%9}, {%0,%1,%2,%3};"
        : "+f"(d[0]), "+f"(d[1]), "+f"(d[2]), "+f"(d[3])
        : "r"(a[0]), "r"(a[1]), "r"(a[2]), "r"(a[3]), "r"(b[0]), "r"(b[1]));
}

__device__ __forceinline__ void split2(float x, float y, uint32_t& hi, uint32_t& lo) {
    __nv_bfloat16 hx = __float2bfloat16(x), hy = __float2bfloat16(y);
    __nv_bfloat16 lx = __float2bfloat16(x - __bfloat162float(hx));
    __nv_bfloat16 ly = __float2bfloat16(y - __bfloat162float(hy));
    hi = (uint32_t)__bfloat16_as_ushort(hx) | ((uint32_t)__bfloat16_as_ushort(hy) << 16);
    lo = (uint32_t)__bfloat16_as_ushort(lx) | ((uint32_t)__bfloat16_as_ushort(ly) << 16);
}

// ================= HMMA 1x1-conv GEMM =================
// Y[b][m][n] = sum_k W[m][k] X[b][k][n] + bias[m].  K = 256, M mult of 128, N arbitrary.
// Block 128x128, 8 warps (warp tile 64x32), K chunks of 32, bf16 Markidis split (3 mma).
#define AS 40   // SMEM row stride in halves (32 k + 8 pad), 80 bytes (16B aligned)

__global__ __launch_bounds__(256) void conv_mma_k(
    const float* __restrict__ W, const float* __restrict__ X,
    const float* __restrict__ bias, float* __restrict__ Y, int M, int N)
{
    __shared__ __align__(16) uint16_t Ah[128 * AS], Al[128 * AS], Bh[128 * AS], Bl[128 * AS];

    const uint32_t uAh = smem_u32(Ah), uAl = smem_u32(Al);
    const uint32_t uBh = smem_u32(Bh), uBl = smem_u32(Bl);

    int t = threadIdx.x, w = t >> 5, l = t & 31;
    int wm = w & 1, wn = w >> 1;              // warp tile: m = wm*64, n = wn*32
    int m0 = blockIdx.y * 128, n0 = blockIdx.x * 128, bz = blockIdx.z;
    const float* Xb = X + (long)bz * 256 * N;
    float* Yb = Y + (long)bz * M * N;

    // loader A: row = t>>1 (0..127), k-half = (t&1)*16
    int arow = t >> 1, akh = (t & 1) * 16;
    // loader B: n group = (t&31)*4, k group = (t>>5)*4
    int bng = (t & 31) * 4, bkg = (t >> 5) * 4;

    float acc[4][4][4];
#pragma unroll
    for (int i = 0; i < 4; i++)
#pragma unroll
        for (int j = 0; j < 4; j++)
#pragma unroll
            for (int r = 0; r < 4; r++) acc[i][j][r] = 0.f;

    // ldmatrix lane addressing
    int a_row_l = l & 15, a_k_l = (l >> 4) * 8;
    int grp = l >> 3;
    int b_n_l = (grp >> 1) * 8 + (l & 7), b_k_l = (grp & 1) * 8;

#pragma unroll 1
    for (int c = 0; c < 8; c++) {
        int k0 = c * 32;

        // ---- A tile: W[m0+arow][k0+akh .. +15] -> bf16 hi/lo ----
        {
            const float* wp = W + (long)(m0 + arow) * 256 + k0 + akh;
            uint32_t* hp = (uint32_t*)&Ah[arow * AS + akh];
            uint32_t* lp = (uint32_t*)&Al[arow * AS + akh];
#pragma unroll
            for (int i = 0; i < 4; i++) {
                float4 f = *(const float4*)(wp + i * 4);
                uint32_t h0, l0, h1, l1;
                split2(f.x, f.y, h0, l0);
                split2(f.z, f.w, h1, l1);
                hp[i * 2] = h0; hp[i * 2 + 1] = h1;
                lp[i * 2] = l0; lp[i * 2 + 1] = l1;
            }
        }
        // ---- B tile (transpose): Bs[n][k] = X[k0+k][n0+n] -> bf16 hi/lo ----
        {
            float v[4][4];   // [k][n]
            int nb = n0 + bng;
            if (nb + 3 < N) {
#pragma unroll
                for (int i = 0; i < 4; i++) {
                    float4 f = *(const float4*)(Xb + (long)(k0 + bkg + i) * N + nb);
                    v[i][0] = f.x; v[i][1] = f.y; v[i][2] = f.z; v[i][3] = f.w;
                }
            } else {
#pragma unroll
                for (int i = 0; i < 4; i++)
#pragma unroll
                    for (int j = 0; j < 4; j++)
                        v[i][j] = (nb + j < N) ? Xb[(long)(k0 + bkg + i) * N + nb + j] : 0.f;
            }
#pragma unroll
            for (int j = 0; j < 4; j++) {
                uint32_t h0, l0, h1, l1;
                split2(v[0][j], v[1][j], h0, l0);
                split2(v[2][j], v[3][j], h1, l1);
                int off = (bng + j) * AS + bkg;
                *(uint32_t*)&Bh[off] = h0; *(uint32_t*)&Bh[off + 2] = h1;
                *(uint32_t*)&Bl[off] = l0; *(uint32_t*)&Bl[off + 2] = l1;
            }
        }
        __syncthreads();

        // ---- compute: 2 k-steps of 16 ----
#pragma unroll
        for (int ks = 0; ks < 2; ks++) {
            uint32_t ah[4][4], al[4][4], bh[2][4], bl[2][4];
#pragma unroll
            for (int i = 0; i < 4; i++) {
                uint32_t off = (uint32_t)(((wm * 64 + i * 16 + a_row_l) * AS + ks * 16 + a_k_l) * 2);
                LDSM_X4(ah[i][0], ah[i][1], ah[i][2], ah[i][3], uAh + off);
                LDSM_X4(al[i][0], al[i][1], al[i][2], al[i][3], uAl + off);
            }
#pragma unroll
            for (int jj = 0; jj < 2; jj++) {
                uint32_t off = (uint32_t)(((wn * 32 + jj * 16 + b_n_l) * AS + ks * 16 + b_k_l) * 2);
                LDSM_X4(bh[jj][0], bh[jj][1], bh[jj][2], bh[jj][3], uBh + off);
                LDSM_X4(bl[jj][0], bl[jj][1], bl[jj][2], bl[jj][3], uBl + off);
            }
#pragma unroll
            for (int i = 0; i < 4; i++)
#pragma unroll
                for (int j = 0; j < 4; j++) {
                    const uint32_t* bhf = &bh[j >> 1][(j & 1) * 2];
                    const uint32_t* blf = &bl[j >> 1][(j & 1) * 2];
                    mma_bf16(acc[i][j], ah[i], bhf);
                    mma_bf16(acc[i][j], ah[i], blf);
                    mma_bf16(acc[i][j], al[i], bhf);
                }
        }
        __syncthreads();
    }

    // ---- epilogue ----
    int mrow = l >> 2, ncol = (l & 3) * 2;
#pragma unroll
    for (int i = 0; i < 4; i++) {
        int m = m0 + wm * 64 + i * 16 + mrow;
        float bv0 = bias[m], bv8 = bias[m + 8];
        float* y0 = Yb + (long)m * N;
        float* y8 = Yb + (long)(m + 8) * N;
#pragma unroll
        for (int j = 0; j < 4; j++) {
            int n = n0 + wn * 32 + j * 8 + ncol;
            if (n < N) {
                y0[n] = acc[i][j][0] + bv0;
                y8[n] = acc[i][j][2] + bv8;
            }
            if (n + 1 < N) {
                y0[n + 1] = acc[i][j][1] + bv0;
                y8[n + 1] = acc[i][j][3] + bv8;
            }
        }
    }
}

// ================= fused flash attention (fp32) =================
#define QT 128
#define QS_STRIDE 132
#define KS_STRIDE 204
#define VS_STRIDE 208
#define PS_STRIDE 200
#define ATTN_SMEM_BYTES ((32 * QS_STRIDE + 32 * KS_STRIDE + 32 * VS_STRIDE + QT * PS_STRIDE) * 4)

__global__ __launch_bounds__(256) void attn_k(
    const float* __restrict__ q, const float* __restrict__ kv, float* __restrict__ gf)
{
    extern __shared__ float sm[];
    float* Qs  = sm;
    float* Kst = Qs + 32 * QS_STRIDE;
    float* Vst = Kst + 32 * KS_STRIDE;
    float* Ps  = Vst + 32 * VS_STRIDE;

    int bh = blockIdx.y;
    int b = bh >> 3, h = bh & 7;
    int s0 = blockIdx.x * QT;
    const float* qb = q  + ((long)b * DIMC + h * DH) * HW;
    const float* kb = kv + ((long)b * 2 * DIMC + h * DH) * SP;
    const float* vb = kb + (long)DIMC * SP;
    float* gfb = gf + ((long)b * DIMC + h * DH) * HW;

    int t = threadIdx.x;

    {
        int d = t >> 3;
        int ss = (t & 7) * 16;
#pragma unroll
        for (int u = 0; u < 16; u++) {
            int s = s0 + ss + u;
            Qs[d * QS_STRIDE + ss + u] = (s < HW) ? qb[(long)d * HW + s] * SCAL : 0.f;
        }
        int kbase = (t & 7) * 25;
#pragma unroll
        for (int u = 0; u < 25; u++) {
            int key = kbase + u;
            if (key < SP) {
                Kst[d * KS_STRIDE + key] = kb[(long)d * SP + key];
                Vst[d * VS_STRIDE + key] = vb[(long)d * SP + key];
            }
        }
    }
    __syncthreads();

    // S = Q^T K
    {
        int ty = t >> 4, tx = t & 15;
#pragma unroll
        for (int kc = 0; kc < 4; kc++) {
            int kn0 = kc * 64;
            if (kc == 3 && tx != 0) break;
            float acc[8][4];
#pragma unroll
            for (int i = 0; i < 8; i++)
#pragma unroll
                for (int j = 0; j < 4; j++) acc[i][j] = 0.f;
#pragma unroll
            for (int kk = 0; kk < 32; kk++) {
                float4 a0 = *(const float4*)&Qs[kk * QS_STRIDE + ty * 8];
                float4 a1 = *(const float4*)&Qs[kk * QS_STRIDE + ty * 8 + 4];
                float4 bb = *(const float4*)&Kst[kk * KS_STRIDE + kn0 + tx * 4];
                float av[8] = {a0.x, a0.y, a0.z, a0.w, a1.x, a1.y, a1.z, a1.w};
                float bv[4] = {bb.x, bb.y, bb.z, bb.w};
#pragma unroll
                for (int i = 0; i < 8; i++)
#pragma unroll
                    for (int j = 0; j < 4; j++) acc[i][j] += av[i] * bv[j];
            }
#pragma unroll
            for (int i = 0; i < 8; i++)
                *(float4*)&Ps[(ty * 8 + i) * PS_STRIDE + kn0 + tx * 4] =
                    make_float4(acc[i][0], acc[i][1], acc[i][2], acc[i][3]);
        }
    }
    __syncthreads();

    // softmax rows
    {
        int w = t >> 5, ln = t & 31;
        for (int rr = 0; rr < 16; rr++) {
            float* row = Ps + (w * 16 + rr) * PS_STRIDE;
            float v[7];
            float mx = -1e30f;
#pragma unroll
            for (int u = 0; u < 7; u++) {
                int idx = ln + 32 * u;
                v[u] = (idx < SP) ? row[idx] : -1e30f;
                mx = fmaxf(mx, v[u]);
            }
#pragma unroll
            for (int off = 16; off; off >>= 1) mx = fmaxf(mx, __shfl_xor_sync(0xffffffffu, mx, off));
            float s = 0.f;
#pragma unroll
            for (int u = 0; u < 7; u++) {
                int idx = ln + 32 * u;
                v[u] = (idx < SP) ? __expf(v[u] - mx) : 0.f;
                s += v[u];
            }
#pragma unroll
            for (int off = 16; off; off >>= 1) s += __shfl_xor_sync(0xffffffffu, s, off);
            float inv = 1.f / s;
#pragma unroll
            for (int u = 0; u < 7; u++) {
                int idx = ln + 32 * u;
                if (idx < SP) row[idx] = v[u] * inv;
            }
        }
    }
    __syncthreads();

    // O = P V^T, float4 along key
    {
        int ty = t >> 3;
        int tx = t & 7;
        float o[4][4];
#pragma unroll
        for (int i = 0; i < 4; i++)
#pragma unroll
            for (int j = 0; j < 4; j++) o[i][j] = 0.f;
        for (int key = 0; key < SP; key += 4) {
            float4 a[4], v4[4];
#pragma unroll
            for (int i = 0; i < 4; i++) a[i] = *(const float4*)&Ps[(ty * 4 + i) * PS_STRIDE + key];
#pragma unroll
            for (int j = 0; j < 4; j++) v4[j] = *(const float4*)&Vst[(tx * 4 + j) * VS_STRIDE + key];
#pragma unroll
            for (int i = 0; i < 4; i++)
#pragma unroll
                for (int j = 0; j < 4; j++)
                    o[i][j] += a[i].x * v4[j].x + a[i].y * v4[j].y + a[i].z * v4[j].z + a[i].w * v4[j].w;
        }
#pragma unroll
        for (int i = 0; i < 4; i++) {
            int s = s0 + ty * 4 + i;
            if (s < HW) {
#pragma unroll
                for (int j = 0; j < 4; j++)
                    gfb[(long)(tx * 4 + j) * HW + s] = o[i][j];
            }
        }
    }
}

// ================= depthwise 5x5 (+BN) =================
__global__ void dwconv_bn_k(
    const float* __restrict__ x, const float* __restrict__ w, const float* __restrict__ cb,
    const float* __restrict__ bng, const float* __restrict__ bnb,
    const float* __restrict__ bnm, const float* __restrict__ bnv,
    float* __restrict__ y,
    int Hin, int Win, int Hout, int Wout, int stride, int useBn)
{
    long idx = (long)blockIdx.x * blockDim.x + threadIdx.x;
    long total = (long)BATCH * DIMC * Hout * Wout;
    if (idx >= total) return;
    int ow = idx % Wout;
    long r = idx / Wout;
    int oh = r % Hout; r /= Hout;
    int c = r % DIMC;
    long bc = idx / ((long)Hout * Wout);
    const float* xp = x + bc * Hin * Win;
    const float* wp = w + c * 25;
    float acc = cb[c];
    int ih0 = oh * stride - 2, iw0 = ow * stride - 2;
#pragma unroll
    for (int kh = 0; kh < 5; kh++) {
        int ih = ih0 + kh;
        if (ih < 0 || ih >= Hin) continue;
#pragma unroll
        for (int kw = 0; kw < 5; kw++) {
            int iw = iw0 + kw;
            if (iw < 0 || iw >= Win) continue;
            acc += xp[ih * Win + iw] * wp[kh * 5 + kw];
        }
    }
    if (useBn) {
        float sc = bng[c] * rsqrtf(bnv[c] + 1e-5f);
        acc = (acc - bnm[c]) * sc + bnb[c];
    }
    y[idx] = acc;
}

// ================= local mixer + gating =================
__global__ void gate_k(
    const float* __restrict__ qloc, const float* __restrict__ gf,
    const float* __restrict__ lw, const float* __restrict__ lb,
    float* __restrict__ out)
{
    long idx = (long)blockIdx.x * blockDim.x + threadIdx.x;
    if (idx >= (long)BATCH * DIMC * HW) return;
    int s = idx % HW;
    int c = (idx / HW) % DIMC;
    int ow = s % WW, oh = s / WW;
    const float* xp = qloc + (idx / HW) * HW;
    const float* wp = lw + c * 25;
    float acc = lb[c];
#pragma unroll
    for (int kh = 0; kh < 5; kh++) {
        int ih = oh - 2 + kh;
        if (ih < 0 || ih >= HH) continue;
#pragma unroll
        for (int kw = 0; kw < 5; kw++) {
            int iw = ow - 2 + kw;
            if (iw < 0 || iw >= WW) continue;
            acc += xp[ih * WW + iw] * wp[kh * 5 + kw];
        }
    }
    float l = acc;
    float lf = l * (1.f / (1.f + __expf(-l)));
    float g = gf[idx];
    float gated = lf * (1.f / (1.f + __expf(-g)));
    out[idx] = gated * g;
}

// ================= host =================
static inline int cdiv(int a, int b) { return (a + b - 1) / b; }

extern "C" void kernel_launch(void* const* d_in, const int* in_sizes, int n_in,
                              void* d_out, int out_size)
{
    const float* x     = (const float*)d_in[0];
    const float* q_w   = (const float*)d_in[1];
    const float* q_b   = (const float*)d_in[2];
    const float* kv_w  = (const float*)d_in[3];
    const float* kv_b  = (const float*)d_in[4];
    const float* p0_w  = (const float*)d_in[5];
    const float* p0_b  = (const float*)d_in[6];
    const float* bn0_g = (const float*)d_in[7];
    const float* bn0_b = (const float*)d_in[8];
    const float* bn0_m = (const float*)d_in[9];
    const float* bn0_v = (const float*)d_in[10];
    const float* pl0_w = (const float*)d_in[11];
    const float* pl0_b = (const float*)d_in[12];
    const float* p1_w  = (const float*)d_in[13];
    const float* p1_b  = (const float*)d_in[14];
    const float* bn1_g = (const float*)d_in[15];
    const float* bn1_b = (const float*)d_in[16];
    const float* bn1_m = (const float*)d_in[17];
    const float* bn1_v = (const float*)d_in[18];
    const float* loc_w = (const float*)d_in[19];
    const float* loc_b = (const float*)d_in[20];
    const float* mix_w = (const float*)d_in[21];
    const float* mix_b = (const float*)d_in[22];
    float* out = (float*)d_out;

    float *q, *p28a, *p28b, *p14, *kv, *gf, *mixin;
    cudaGetSymbolAddress((void**)&q,     g_q);
    cudaGetSymbolAddress((void**)&p28a,  g_p28a);
    cudaGetSymbolAddress((void**)&p28b,  g_p28b);
    cudaGetSymbolAddress((void**)&p14,   g_p14);
    cudaGetSymbolAddress((void**)&kv,    g_kv);
    cudaGetSymbolAddress((void**)&gf,    g_gf);
    cudaGetSymbolAddress((void**)&mixin, g_mixin);

    cudaFuncSetAttribute(attn_k, cudaFuncAttributeMaxDynamicSharedMemorySize, (int)ATTN_SMEM_BYTES);

    dim3 tb(256);

    // 1) q_local = 1x1 conv (HMMA)
    conv_mma_k<<<dim3(cdiv(HW, 128), DIMC / 128, BATCH), tb>>>(q_w, x, q_b, q, DIMC, HW);

    // 2) p0 dwconv s2 + BN0 (56->28)
    dwconv_bn_k<<<cdiv(BATCH * DIMC * S28, 256), tb>>>(
        x, p0_w, p0_b, bn0_g, bn0_b, bn0_m, bn0_v, p28a, HH, WW, H28, H28, 2, 1);

    // 3) pl0 1x1 conv (HMMA)
    conv_mma_k<<<dim3(cdiv(S28, 128), DIMC / 128, BATCH), tb>>>(pl0_w, p28a, pl0_b, p28b, DIMC, S28);

    // 4) p1 dwconv s2 + BN1 (28->14)
    dwconv_bn_k<<<cdiv(BATCH * DIMC * SP, 256), tb>>>(
        p28b, p1_w, p1_b, bn1_g, bn1_b, bn1_m, bn1_v, p14, H28, H28, HP, HP, 2, 1);

    // 5) kv 1x1 conv (HMMA, M=512)
    conv_mma_k<<<dim3(cdiv(SP, 128), 2 * DIMC / 128, BATCH), tb>>>(kv_w, p14, kv_b, kv, 2 * DIMC, SP);

    // 6) fused attention
    attn_k<<<dim3(cdiv(HW, QT), BATCH * HEADS), tb, ATTN_SMEM_BYTES>>>(q, kv, gf);

    // 7) local mixer + gating
    gate_k<<<cdiv(BATCH * DIMC * HW, 256), tb>>>(q, gf, loc_w, loc_b, mixin);

    // 8) mix 1x1 conv (HMMA) -> out
    conv_mma_k<<<dim3(cdiv(HW, 128), DIMC / 128, BATCH), tb>>>(mix_w, mixin, mix_b, out, DIMC, HW);
}

// round 12
// speedup vs baseline: 1.4533x; 1.4533x over previous
#include <cuda_runtime.h>
#include <cuda_bf16.h>
#include <cstdint>
#include <math.h>

#define BATCH 16
#define DIMC 256
#define HH 56
#define WW 56
#define HEADS 8
#define DH 32
#define HW 3136
#define H28 28
#define S28 784
#define HP 14
#define SP 196
#define SCAL 0.17677669529663687f

// ---------------- fp32 scratch ----------------
__device__ float g_q    [BATCH * DIMC * HW];
__device__ float g_p28b [BATCH * DIMC * S28];
__device__ float g_kv   [BATCH * 2 * DIMC * SP];
__device__ float g_gf   [BATCH * DIMC * HW];

// ---------------- bf16 hi/lo scratch (GEMM inputs) ----------------
__device__ __nv_bfloat16 g_xh  [BATCH * DIMC * HW],  g_xl  [BATCH * DIMC * HW];
__device__ __nv_bfloat16 g_p28h[BATCH * DIMC * S28], g_p28l[BATCH * DIMC * S28];
__device__ __nv_bfloat16 g_p14h[BATCH * DIMC * SP],  g_p14l[BATCH * DIMC * SP];
__device__ __nv_bfloat16 g_mixh[BATCH * DIMC * HW],  g_mixl[BATCH * DIMC * HW];
__device__ __nv_bfloat16 g_wqh [DIMC * DIMC], g_wql [DIMC * DIMC];
__device__ __nv_bfloat16 g_wph [DIMC * DIMC], g_wpl [DIMC * DIMC];
__device__ __nv_bfloat16 g_wkh [2 * DIMC * DIMC], g_wkl [2 * DIMC * DIMC];
__device__ __nv_bfloat16 g_wmh [DIMC * DIMC], g_wml [DIMC * DIMC];

// ================= helpers =================
__device__ __forceinline__ uint32_t smem_u32(const void* p) {
    uint32_t a;
    asm("{ .reg .u64 t; cvta.to.shared.u64 t, %1; cvt.u32.u64 %0, t; }" : "=r"(a) : "l"(p));
    return a;
}

#define LDSM_X4(r0, r1, r2, r3, addr) \
    asm volatile("ldmatrix.sync.aligned.m8n8.x4.shared.b16 {%0,%1,%2,%3}, [%4];" \
        : "=r"(r0), "=r"(r1), "=r"(r2), "=r"(r3) : "r"(addr))

#define LDSM_X4_T(r0, r1, r2, r3, addr) \
    asm volatile("ldmatrix.sync.aligned.m8n8.x4.trans.shared.b16 {%0,%1,%2,%3}, [%4];" \
        : "=r"(r0), "=r"(r1), "=r"(r2), "=r"(r3) : "r"(addr))

__device__ __forceinline__ void mma_bf16(float* d, const uint32_t* a, const uint32_t* b) {
    asm volatile(
        "mma.sync.aligned.m16n8k16.row.col.f32.bf16.bf16.f32 "
        "{%0,%1,%2,%3}, {%4,%5,%6,%7}, {%8,%9}, {%0,%1,%2,%3};"
        : "+f"(d[0]), "+f"(d[1]), "+f"(d[2]), "+f"(d[3])
        : "r"(a[0]), "r"(a[1]), "r"(a[2]), "r"(a[3]), "r"(b[0]), "r"(b[1]));
}

__device__ __forceinline__ void splitv(float v, __nv_bfloat16& h, __nv_bfloat16& lo) {
    h = __float2bfloat16(v);
    lo = __float2bfloat16(v - __bfloat162float(h));
}

// ================= elementwise fp32 -> bf16 hi/lo split =================
__global__ void split_k(const float* __restrict__ src,
                        __nv_bfloat16* __restrict__ h, __nv_bfloat16* __restrict__ lo, long n)
{
    long i = (long)blockIdx.x * blockDim.x + threadIdx.x;
    if (i < n) {
        float v = src[i];
        __nv_bfloat16 hv, lv;
        splitv(v, hv, lv);
        h[i] = hv; lo[i] = lv;
    }
}

// ================= HMMA 1x1-conv GEMM (preconverted bf16 inputs) =================
// Y[b][m][n] = sum_k (Wh+Wl)[m][k] * (Xh+Xl)[b][k][n] + bias[m]   (Markidis 3-term)
// K = 256, block 128x128, 8 warps (warp 64x32), K chunks of 32.
#define AS 40    // A smem stride in halves (32 k + 8 pad)
#define BS 136   // B smem stride in halves (128 n + 8 pad)

__global__ __launch_bounds__(256) void conv_mma2_k(
    const __nv_bfloat16* __restrict__ Wh, const __nv_bfloat16* __restrict__ Wl,
    const __nv_bfloat16* __restrict__ Xh, const __nv_bfloat16* __restrict__ Xl,
    const float* __restrict__ bias, float* __restrict__ Y, int M, int N)
{
    __shared__ __align__(16) uint16_t Ah[128 * AS], Al[128 * AS];
    __shared__ __align__(16) uint16_t Bh[32 * BS], Bl[32 * BS];

    const uint32_t uAh = smem_u32(Ah), uAl = smem_u32(Al);
    const uint32_t uBh = smem_u32(Bh), uBl = smem_u32(Bl);

    int t = threadIdx.x, w = t >> 5, l = t & 31;
    int wm = w & 1, wn = w >> 1;
    int m0 = blockIdx.y * 128, n0 = blockIdx.x * 128, bz = blockIdx.z;
    const __nv_bfloat16* XbH = Xh + (long)bz * 256 * N;
    const __nv_bfloat16* XbL = Xl + (long)bz * 256 * N;
    float* Yb = Y + (long)bz * M * N;

    // A loader: row = t>>1, k-half = (t&1)*16
    int arow = t >> 1, akh = (t & 1) * 16;
    // B loader: k row = t>>3 (0..31), n group = (t&7)*16
    int bkr = t >> 3, bng = (t & 7) * 16;
    bool nAligned = (N & 7) == 0;

    float acc[4][4][4];
#pragma unroll
    for (int i = 0; i < 4; i++)
#pragma unroll
        for (int j = 0; j < 4; j++)
#pragma unroll
            for (int r = 0; r < 4; r++) acc[i][j][r] = 0.f;

    // A ldmatrix lanes (row-major, non-trans)
    int a_row_l = l & 15, a_k_l = (l >> 4) * 8;
    // B ldmatrix lanes (K-major, trans): group g = l>>3, matrices: k+=(g&1)*8, n+=(g>>1)*8
    int g = l >> 3;
    int b_k_l = (g & 1) * 8 + (l & 7), b_n_l = (g >> 1) * 8;

#pragma unroll 1
    for (int c = 0; c < 8; c++) {
        int k0 = c * 32;

        // ---- A tile copy: Wh/Wl[(m0+arow)*256 + k0+akh .. +15] ----
        {
            long off = (long)(m0 + arow) * 256 + k0 + akh;
            const uint4* sh = (const uint4*)(Wh + off);
            const uint4* sl = (const uint4*)(Wl + off);
            uint4* dh = (uint4*)&Ah[arow * AS + akh];
            uint4* dl = (uint4*)&Al[arow * AS + akh];
            dh[0] = sh[0]; dh[1] = sh[1];
            dl[0] = sl[0]; dl[1] = sl[1];
        }
        // ---- B tile copy (K-major): Bs[k][n] = X[(k0+k)*N + n0+bng .. +15] ----
        {
            long off = (long)(k0 + bkr) * N + n0 + bng;
            uint16_t* dh = &Bh[bkr * BS + bng];
            uint16_t* dl = &Bl[bkr * BS + bng];
            if (n0 + bng + 16 <= N && nAligned) {
                const uint4* sh = (const uint4*)(XbH + off);
                const uint4* sl = (const uint4*)(XbL + off);
                ((uint4*)dh)[0] = sh[0]; ((uint4*)dh)[1] = sh[1];
                ((uint4*)dl)[0] = sl[0]; ((uint4*)dl)[1] = sl[1];
            } else {
#pragma unroll
                for (int u = 0; u < 16; u++) {
                    bool in = (n0 + bng + u) < N;
                    dh[u] = in ? ((const uint16_t*)XbH)[off + u] : (uint16_t)0;
                    dl[u] = in ? ((const uint16_t*)XbL)[off + u] : (uint16_t)0;
                }
            }
        }
        __syncthreads();

        // ---- compute: 2 k-steps of 16 ----
#pragma unroll
        for (int ks = 0; ks < 2; ks++) {
            uint32_t ah[4][4], al[4][4], bh[2][4], bl[2][4];
#pragma unroll
            for (int i = 0; i < 4; i++) {
                uint32_t off = (uint32_t)(((wm * 64 + i * 16 + a_row_l) * AS + ks * 16 + a_k_l) * 2);
                LDSM_X4(ah[i][0], ah[i][1], ah[i][2], ah[i][3], uAh + off);
                LDSM_X4(al[i][0], al[i][1], al[i][2], al[i][3], uAl + off);
            }
#pragma unroll
            for (int jj = 0; jj < 2; jj++) {
                uint32_t off = (uint32_t)(((ks * 16 + b_k_l) * BS + wn * 32 + jj * 16 + b_n_l) * 2);
                LDSM_X4_T(bh[jj][0], bh[jj][1], bh[jj][2], bh[jj][3], uBh + off);
                LDSM_X4_T(bl[jj][0], bl[jj][1], bl[jj][2], bl[jj][3], uBl + off);
            }
#pragma unroll
            for (int i = 0; i < 4; i++)
#pragma unroll
                for (int j = 0; j < 4; j++) {
                    const uint32_t* bhf = &bh[j >> 1][(j & 1) * 2];
                    const uint32_t* blf = &bl[j >> 1][(j & 1) * 2];
                    mma_bf16(acc[i][j], ah[i], bhf);
                    mma_bf16(acc[i][j], ah[i], blf);
                    mma_bf16(acc[i][j], al[i], bhf);
                }
        }
        __syncthreads();
    }

    // ---- epilogue (layout verified in R8) ----
    int mrow = l >> 2, ncol = (l & 3) * 2;
#pragma unroll
    for (int i = 0; i < 4; i++) {
        int m = m0 + wm * 64 + i * 16 + mrow;
        float bv0 = bias[m], bv8 = bias[m + 8];
        float* y0 = Yb + (long)m * N;
        float* y8 = Yb + (long)(m + 8) * N;
#pragma unroll
        for (int j = 0; j < 4; j++) {
            int n = n0 + wn * 32 + j * 8 + ncol;
            if (n < N) {
                y0[n] = acc[i][j][0] + bv0;
                y8[n] = acc[i][j][2] + bv8;
            }
            if (n + 1 < N) {
                y0[n + 1] = acc[i][j][1] + bv0;
                y8[n + 1] = acc[i][j][3] + bv8;
            }
        }
    }
}

// ================= fused flash attention (fp32, R3-measured config) =================
#define QT 128
#define QS_STRIDE 132
#define KS_STRIDE 204
#define VS_STRIDE 205
#define PS_STRIDE 197
#define ATTN_SMEM_BYTES ((32 * QS_STRIDE + 32 * KS_STRIDE + 32 * VS_STRIDE + QT * PS_STRIDE) * 4)

__global__ __launch_bounds__(256) void attn_k(
    const float* __restrict__ q, const float* __restrict__ kv, float* __restrict__ gf)
{
    extern __shared__ float sm[];
    float* Qs  = sm;
    float* Kst = Qs + 32 * QS_STRIDE;
    float* Vst = Kst + 32 * KS_STRIDE;
    float* Ps  = Vst + 32 * VS_STRIDE;

    int bh = blockIdx.y;
    int b = bh >> 3, h = bh & 7;
    int s0 = blockIdx.x * QT;
    const float* qb = q  + ((long)b * DIMC + h * DH) * HW;
    const float* kb = kv + ((long)b * 2 * DIMC + h * DH) * SP;
    const float* vb = kb + (long)DIMC * SP;
    float* gfb = gf + ((long)b * DIMC + h * DH) * HW;

    int t = threadIdx.x;

    {
        int d = t >> 3;
        int ss = (t & 7) * 16;
#pragma unroll
        for (int u = 0; u < 16; u++) {
            int s = s0 + ss + u;
            Qs[d * QS_STRIDE + ss + u] = (s < HW) ? qb[(long)d * HW + s] * SCAL : 0.f;
        }
        int kbase = (t & 7) * 25;
#pragma unroll
        for (int u = 0; u < 25; u++) {
            int key = kbase + u;
            if (key < SP) {
                Kst[d * KS_STRIDE + key] = kb[(long)d * SP + key];
                Vst[d * VS_STRIDE + key] = vb[(long)d * SP + key];
            }
        }
    }
    __syncthreads();

    // S = Q^T K
    {
        int ty = t >> 4, tx = t & 15;
#pragma unroll
        for (int kc = 0; kc < 4; kc++) {
            int kn0 = kc * 64;
            if (kc == 3 && tx != 0) break;
            float acc[8][4];
#pragma unroll
            for (int i = 0; i < 8; i++)
#pragma unroll
                for (int j = 0; j < 4; j++) acc[i][j] = 0.f;
#pragma unroll
            for (int kk = 0; kk < 32; kk++) {
                float4 a0 = *(const float4*)&Qs[kk * QS_STRIDE + ty * 8];
                float4 a1 = *(const float4*)&Qs[kk * QS_STRIDE + ty * 8 + 4];
                float4 bb = *(const float4*)&Kst[kk * KS_STRIDE + kn0 + tx * 4];
                float av[8] = {a0.x, a0.y, a0.z, a0.w, a1.x, a1.y, a1.z, a1.w};
                float bv[4] = {bb.x, bb.y, bb.z, bb.w};
#pragma unroll
                for (int i = 0; i < 8; i++)
#pragma unroll
                    for (int j = 0; j < 4; j++) acc[i][j] += av[i] * bv[j];
            }
#pragma unroll
            for (int i = 0; i < 8; i++)
#pragma unroll
                for (int j = 0; j < 4; j++)
                    Ps[(ty * 8 + i) * PS_STRIDE + kn0 + tx * 4 + j] = acc[i][j];
        }
    }
    __syncthreads();

    // softmax rows
    {
        int w = t >> 5, ln = t & 31;
        for (int rr = 0; rr < 16; rr++) {
            float* row = Ps + (w * 16 + rr) * PS_STRIDE;
            float v[7];
            float mx = -1e30f;
#pragma unroll
            for (int u = 0; u < 7; u++) {
                int idx = ln + 32 * u;
                v[u] = (idx < SP) ? row[idx] : -1e30f;
                mx = fmaxf(mx, v[u]);
            }
#pragma unroll
            for (int off = 16; off; off >>= 1) mx = fmaxf(mx, __shfl_xor_sync(0xffffffffu, mx, off));
            float s = 0.f;
#pragma unroll
            for (int u = 0; u < 7; u++) {
                int idx = ln + 32 * u;
                v[u] = (idx < SP) ? __expf(v[u] - mx) : 0.f;
                s += v[u];
            }
#pragma unroll
            for (int off = 16; off; off >>= 1) s += __shfl_xor_sync(0xffffffffu, s, off);
            float inv = 1.f / s;
#pragma unroll
            for (int u = 0; u < 7; u++) {
                int idx = ln + 32 * u;
                if (idx < SP) row[idx] = v[u] * inv;
            }
        }
    }
    __syncthreads();

    // O = P V^T
    {
        int ty = t >> 3;
        int tx = t & 7;
        float o[4][4];
#pragma unroll
        for (int i = 0; i < 4; i++)
#pragma unroll
            for (int j = 0; j < 4; j++) o[i][j] = 0.f;
#pragma unroll 4
        for (int key = 0; key < SP; key++) {
            float av[4], bv[4];
#pragma unroll
            for (int i = 0; i < 4; i++) av[i] = Ps[(ty * 4 + i) * PS_STRIDE + key];
#pragma unroll
            for (int j = 0; j < 4; j++) bv[j] = Vst[(tx * 4 + j) * VS_STRIDE + key];
#pragma unroll
            for (int i = 0; i < 4; i++)
#pragma unroll
                for (int j = 0; j < 4; j++) o[i][j] += av[i] * bv[j];
        }
#pragma unroll
        for (int i = 0; i < 4; i++) {
            int s = s0 + ty * 4 + i;
            if (s < HW) {
#pragma unroll
                for (int j = 0; j < 4; j++)
                    gfb[(long)(tx * 4 + j) * HW + s] = o[i][j];
            }
        }
    }
}

// ================= depthwise 5x5 + BN, bf16 hi/lo output =================
__global__ void dwconv_bn_k(
    const float* __restrict__ x, const float* __restrict__ w, const float* __restrict__ cb,
    const float* __restrict__ bng, const float* __restrict__ bnb,
    const float* __restrict__ bnm, const float* __restrict__ bnv,
    __nv_bfloat16* __restrict__ yh, __nv_bfloat16* __restrict__ yl,
    int Hin, int Win, int Hout, int Wout, int stride)
{
    long idx = (long)blockIdx.x * blockDim.x + threadIdx.x;
    long total = (long)BATCH * DIMC * Hout * Wout;
    if (idx >= total) return;
    int ow = idx % Wout;
    long r = idx / Wout;
    int oh = r % Hout; r /= Hout;
    int c = r % DIMC;
    long bc = idx / ((long)Hout * Wout);
    const float* xp = x + bc * Hin * Win;
    const float* wp = w + c * 25;
    float acc = cb[c];
    int ih0 = oh * stride - 2, iw0 = ow * stride - 2;
#pragma unroll
    for (int kh = 0; kh < 5; kh++) {
        int ih = ih0 + kh;
        if (ih < 0 || ih >= Hin) continue;
#pragma unroll
        for (int kw = 0; kw < 5; kw++) {
            int iw = iw0 + kw;
            if (iw < 0 || iw >= Win) continue;
            acc += xp[ih * Win + iw] * wp[kh * 5 + kw];
        }
    }
    float sc = bng[c] * rsqrtf(bnv[c] + 1e-5f);
    acc = (acc - bnm[c]) * sc + bnb[c];
    __nv_bfloat16 hv, lv;
    splitv(acc, hv, lv);
    yh[idx] = hv; yl[idx] = lv;
}

// ================= local mixer + gating, bf16 hi/lo output =================
__global__ void gate_k(
    const float* __restrict__ qloc, const float* __restrict__ gf,
    const float* __restrict__ lw, const float* __restrict__ lb,
    __nv_bfloat16* __restrict__ oh2, __nv_bfloat16* __restrict__ ol2)
{
    long idx = (long)blockIdx.x * blockDim.x + threadIdx.x;
    if (idx >= (long)BATCH * DIMC * HW) return;
    int s = idx % HW;
    int c = (idx / HW) % DIMC;
    int ow = s % WW, oh = s / WW;
    const float* xp = qloc + (idx / HW) * HW;
    const float* wp = lw + c * 25;
    float acc = lb[c];
#pragma unroll
    for (int kh = 0; kh < 5; kh++) {
        int ih = oh - 2 + kh;
        if (ih < 0 || ih >= HH) continue;
#pragma unroll
        for (int kw = 0; kw < 5; kw++) {
            int iw = ow - 2 + kw;
            if (iw < 0 || iw >= WW) continue;
            acc += xp[ih * WW + iw] * wp[kh * 5 + kw];
        }
    }
    float l = acc;
    float lf = l * (1.f / (1.f + __expf(-l)));
    float g = gf[idx];
    float gated = lf * (1.f / (1.f + __expf(-g)));
    float v = gated * g;
    __nv_bfloat16 hv, lv;
    splitv(v, hv, lv);
    oh2[idx] = hv; ol2[idx] = lv;
}

// ================= host =================
static inline int cdiv(int a, int b) { return (a + b - 1) / b; }

extern "C" void kernel_launch(void* const* d_in, const int* in_sizes, int n_in,
                              void* d_out, int out_size)
{
    const float* x     = (const float*)d_in[0];
    const float* q_w   = (const float*)d_in[1];
    const float* q_b   = (const float*)d_in[2];
    const float* kv_w  = (const float*)d_in[3];
    const float* kv_b  = (const float*)d_in[4];
    const float* p0_w  = (const float*)d_in[5];
    const float* p0_b  = (const float*)d_in[6];
    const float* bn0_g = (const float*)d_in[7];
    const float* bn0_b = (const float*)d_in[8];
    const float* bn0_m = (const float*)d_in[9];
    const float* bn0_v = (const float*)d_in[10];
    const float* pl0_w = (const float*)d_in[11];
    const float* pl0_b = (const float*)d_in[12];
    const float* p1_w  = (const float*)d_in[13];
    const float* p1_b  = (const float*)d_in[14];
    const float* bn1_g = (const float*)d_in[15];
    const float* bn1_b = (const float*)d_in[16];
    const float* bn1_m = (const float*)d_in[17];
    const float* bn1_v = (const float*)d_in[18];
    const float* loc_w = (const float*)d_in[19];
    const float* loc_b = (const float*)d_in[20];
    const float* mix_w = (const float*)d_in[21];
    const float* mix_b = (const float*)d_in[22];
    float* out = (float*)d_out;

    float *q, *p28b, *kv, *gf;
    cudaGetSymbolAddress((void**)&q,    g_q);
    cudaGetSymbolAddress((void**)&p28b, g_p28b);
    cudaGetSymbolAddress((void**)&kv,   g_kv);
    cudaGetSymbolAddress((void**)&gf,   g_gf);

    __nv_bfloat16 *xh, *xl, *p28h, *p28l, *p14h, *p14l, *mixh, *mixl;
    __nv_bfloat16 *wqh, *wql, *wph, *wpl, *wkh, *wkl, *wmh, *wml;
    cudaGetSymbolAddress((void**)&xh, g_xh);     cudaGetSymbolAddress((void**)&xl, g_xl);
    cudaGetSymbolAddress((void**)&p28h, g_p28h); cudaGetSymbolAddress((void**)&p28l, g_p28l);
    cudaGetSymbolAddress((void**)&p14h, g_p14h); cudaGetSymbolAddress((void**)&p14l, g_p14l);
    cudaGetSymbolAddress((void**)&mixh, g_mixh); cudaGetSymbolAddress((void**)&mixl, g_mixl);
    cudaGetSymbolAddress((void**)&wqh, g_wqh);   cudaGetSymbolAddress((void**)&wql, g_wql);
    cudaGetSymbolAddress((void**)&wph, g_wph);   cudaGetSymbolAddress((void**)&wpl, g_wpl);
    cudaGetSymbolAddress((void**)&wkh, g_wkh);   cudaGetSymbolAddress((void**)&wkl, g_wkl);
    cudaGetSymbolAddress((void**)&wmh, g_wmh);   cudaGetSymbolAddress((void**)&wml, g_wml);

    cudaFuncSetAttribute(attn_k, cudaFuncAttributeMaxDynamicSharedMemorySize, (int)ATTN_SMEM_BYTES);

    dim3 tb(256);

    // 0) pre-split GEMM inputs
    {
        long nx = (long)BATCH * DIMC * HW;
        split_k<<<(int)((nx + 255) / 256), tb>>>(x, xh, xl, nx);
        split_k<<<(DIMC * DIMC + 255) / 256, tb>>>(q_w, wqh, wql, DIMC * DIMC);
        split_k<<<(DIMC * DIMC + 255) / 256, tb>>>(pl0_w, wph, wpl, DIMC * DIMC);
        split_k<<<(2 * DIMC * DIMC + 255) / 256, tb>>>(kv_w, wkh, wkl, 2 * DIMC * DIMC);
        split_k<<<(DIMC * DIMC + 255) / 256, tb>>>(mix_w, wmh, wml, DIMC * DIMC);
    }

    // 1) q_local = 1x1 conv
    conv_mma2_k<<<dim3(cdiv(HW, 128), DIMC / 128, BATCH), tb>>>(wqh, wql, xh, xl, q_b, q, DIMC, HW);

    // 2) p0 dwconv s2 + BN0 (56->28), bf16 out
    dwconv_bn_k<<<cdiv(BATCH * DIMC * S28, 256), tb>>>(
        x, p0_w, p0_b, bn0_g, bn0_b, bn0_m, bn0_v, p28h, p28l, HH, WW, H28, H28, 2);

    // 3) pl0 1x1 conv (fp32 out)
    conv_mma2_k<<<dim3(cdiv(S28, 128), DIMC / 128, BATCH), tb>>>(wph, wpl, p28h, p28l, pl0_b, p28b, DIMC, S28);

    // 4) p1 dwconv s2 + BN1 (28->14), bf16 out
    dwconv_bn_k<<<cdiv(BATCH * DIMC * SP, 256), tb>>>(
        p28b, p1_w, p1_b, bn1_g, bn1_b, bn1_m, bn1_v, p14h, p14l, H28, H28, HP, HP, 2);

    // 5) kv 1x1 conv (M=512)
    conv_mma2_k<<<dim3(cdiv(SP, 128), 2 * DIMC / 128, BATCH), tb>>>(wkh, wkl, p14h, p14l, kv_b, kv, 2 * DIMC, SP);

    // 6) fused attention
    attn_k<<<dim3(cdiv(HW, QT), BATCH * HEADS), tb, ATTN_SMEM_BYTES>>>(q, kv, gf);

    // 7) local mixer + gating, bf16 out
    gate_k<<<cdiv(BATCH * DIMC * HW, 256), tb>>>(q, gf, loc_w, loc_b, mixh, mixl);

    // 8) mix 1x1 conv -> out
    conv_mma2_k<<<dim3(cdiv(HW, 128), DIMC / 128, BATCH), tb>>>(wmh, wml, mixh, mixl, mix_b, out, DIMC, HW);
}

// round 16
// speedup vs baseline: 1.7144x; 1.1797x over previous
#include <cuda_runtime.h>
#include <cuda_bf16.h>
#include <cstdint>
#include <math.h>

#define BATCH 16
#define DIMC 256
#define HH 56
#define WW 56
#define HEADS 8
#define DH 32
#define HW 3136
#define H28 28
#define S28 784
#define HP 14
#define SP 196
#define SCAL 0.17677669529663687f

// ---------------- fp32 scratch ----------------
__device__ float g_q    [BATCH * DIMC * HW];
__device__ float g_p28b [BATCH * DIMC * S28];
__device__ float g_kv   [BATCH * 2 * DIMC * SP];
__device__ float g_gf   [BATCH * DIMC * HW];

// ---------------- bf16 hi/lo scratch (GEMM inputs) ----------------
__device__ __nv_bfloat16 g_xh  [BATCH * DIMC * HW],  g_xl  [BATCH * DIMC * HW];
__device__ __nv_bfloat16 g_p28h[BATCH * DIMC * S28], g_p28l[BATCH * DIMC * S28];
__device__ __nv_bfloat16 g_p14h[BATCH * DIMC * SP],  g_p14l[BATCH * DIMC * SP];
__device__ __nv_bfloat16 g_mixh[BATCH * DIMC * HW],  g_mixl[BATCH * DIMC * HW];
__device__ __nv_bfloat16 g_wqh [DIMC * DIMC], g_wql [DIMC * DIMC];
__device__ __nv_bfloat16 g_wph [DIMC * DIMC], g_wpl [DIMC * DIMC];
__device__ __nv_bfloat16 g_wkh [2 * DIMC * DIMC], g_wkl [2 * DIMC * DIMC];
__device__ __nv_bfloat16 g_wmh [DIMC * DIMC], g_wml [DIMC * DIMC];

// ================= helpers =================
__device__ __forceinline__ uint32_t smem_u32(const void* p) {
    uint32_t a;
    asm("{ .reg .u64 t; cvta.to.shared.u64 t, %1; cvt.u32.u64 %0, t; }" : "=r"(a) : "l"(p));
    return a;
}

#define LDSM_X4(r0, r1, r2, r3, addr) \
    asm volatile("ldmatrix.sync.aligned.m8n8.x4.shared.b16 {%0,%1,%2,%3}, [%4];" \
        : "=r"(r0), "=r"(r1), "=r"(r2), "=r"(r3) : "r"(addr))

#define LDSM_X4_T(r0, r1, r2, r3, addr) \
    asm volatile("ldmatrix.sync.aligned.m8n8.x4.trans.shared.b16 {%0,%1,%2,%3}, [%4];" \
        : "=r"(r0), "=r"(r1), "=r"(r2), "=r"(r3) : "r"(addr))

__device__ __forceinline__ void mma_bf16(float* d, const uint32_t* a, const uint32_t* b) {
    asm volatile(
        "mma.sync.aligned.m16n8k16.row.col.f32.bf16.bf16.f32 "
        "{%0,%1,%2,%3}, {%4,%5,%6,%7}, {%8,%9}, {%0,%1,%2,%3};"
        : "+f"(d[0]), "+f"(d[1]), "+f"(d[2]), "+f"(d[3])
        : "r"(a[0]), "r"(a[1]), "r"(a[2]), "r"(a[3]), "r"(b[0]), "r"(b[1]));
}

__device__ __forceinline__ void splitv(float v, __nv_bfloat16& h, __nv_bfloat16& lo) {
    h = __float2bfloat16(v);
    lo = __float2bfloat16(v - __bfloat162float(h));
}

// ================= elementwise fp32 -> bf16 hi/lo split =================
__global__ void split_k(const float* __restrict__ src,
                        __nv_bfloat16* __restrict__ h, __nv_bfloat16* __restrict__ lo, long n)
{
    long i = (long)blockIdx.x * blockDim.x + threadIdx.x;
    if (i < n) {
        float v = src[i];
        __nv_bfloat16 hv, lv;
        splitv(v, hv, lv);
        h[i] = hv; lo[i] = lv;
    }
}

// ================= HMMA 1x1-conv GEMM (verified R12) =================
#define AS 40
#define BS 136

__global__ __launch_bounds__(256) void conv_mma2_k(
    const __nv_bfloat16* __restrict__ Wh, const __nv_bfloat16* __restrict__ Wl,
    const __nv_bfloat16* __restrict__ Xh, const __nv_bfloat16* __restrict__ Xl,
    const float* __restrict__ bias, float* __restrict__ Y, int M, int N)
{
    __shared__ __align__(16) uint16_t Ah[128 * AS], Al[128 * AS];
    __shared__ __align__(16) uint16_t Bh[32 * BS], Bl[32 * BS];

    const uint32_t uAh = smem_u32(Ah), uAl = smem_u32(Al);
    const uint32_t uBh = smem_u32(Bh), uBl = smem_u32(Bl);

    int t = threadIdx.x, w = t >> 5, l = t & 31;
    int wm = w & 1, wn = w >> 1;
    int m0 = blockIdx.y * 128, n0 = blockIdx.x * 128, bz = blockIdx.z;
    const __nv_bfloat16* XbH = Xh + (long)bz * 256 * N;
    const __nv_bfloat16* XbL = Xl + (long)bz * 256 * N;
    float* Yb = Y + (long)bz * M * N;

    int arow = t >> 1, akh = (t & 1) * 16;
    int bkr = t >> 3, bng = (t & 7) * 16;
    bool nAligned = (N & 7) == 0;

    float acc[4][4][4];
#pragma unroll
    for (int i = 0; i < 4; i++)
#pragma unroll
        for (int j = 0; j < 4; j++)
#pragma unroll
            for (int r = 0; r < 4; r++) acc[i][j][r] = 0.f;

    int a_row_l = l & 15, a_k_l = (l >> 4) * 8;
    int g = l >> 3;
    int b_k_l = (g & 1) * 8 + (l & 7), b_n_l = (g >> 1) * 8;

#pragma unroll 1
    for (int c = 0; c < 8; c++) {
        int k0 = c * 32;
        {
            long off = (long)(m0 + arow) * 256 + k0 + akh;
            const uint4* sh = (const uint4*)(Wh + off);
            const uint4* sl = (const uint4*)(Wl + off);
            uint4* dh = (uint4*)&Ah[arow * AS + akh];
            uint4* dl = (uint4*)&Al[arow * AS + akh];
            dh[0] = sh[0]; dh[1] = sh[1];
            dl[0] = sl[0]; dl[1] = sl[1];
        }
        {
            long off = (long)(k0 + bkr) * N + n0 + bng;
            uint16_t* dh = &Bh[bkr * BS + bng];
            uint16_t* dl = &Bl[bkr * BS + bng];
            if (n0 + bng + 16 <= N && nAligned) {
                const uint4* sh = (const uint4*)(XbH + off);
                const uint4* sl = (const uint4*)(XbL + off);
                ((uint4*)dh)[0] = sh[0]; ((uint4*)dh)[1] = sh[1];
                ((uint4*)dl)[0] = sl[0]; ((uint4*)dl)[1] = sl[1];
            } else {
#pragma unroll
                for (int u = 0; u < 16; u++) {
                    bool in = (n0 + bng + u) < N;
                    dh[u] = in ? ((const uint16_t*)XbH)[off + u] : (uint16_t)0;
                    dl[u] = in ? ((const uint16_t*)XbL)[off + u] : (uint16_t)0;
                }
            }
        }
        __syncthreads();

#pragma unroll
        for (int ks = 0; ks < 2; ks++) {
            uint32_t ah[4][4], al[4][4], bh[2][4], bl[2][4];
#pragma unroll
            for (int i = 0; i < 4; i++) {
                uint32_t off = (uint32_t)(((wm * 64 + i * 16 + a_row_l) * AS + ks * 16 + a_k_l) * 2);
                LDSM_X4(ah[i][0], ah[i][1], ah[i][2], ah[i][3], uAh + off);
                LDSM_X4(al[i][0], al[i][1], al[i][2], al[i][3], uAl + off);
            }
#pragma unroll
            for (int jj = 0; jj < 2; jj++) {
                uint32_t off = (uint32_t)(((ks * 16 + b_k_l) * BS + wn * 32 + jj * 16 + b_n_l) * 2);
                LDSM_X4_T(bh[jj][0], bh[jj][1], bh[jj][2], bh[jj][3], uBh + off);
                LDSM_X4_T(bl[jj][0], bl[jj][1], bl[jj][2], bl[jj][3], uBl + off);
            }
#pragma unroll
            for (int i = 0; i < 4; i++)
#pragma unroll
                for (int j = 0; j < 4; j++) {
                    const uint32_t* bhf = &bh[j >> 1][(j & 1) * 2];
                    const uint32_t* blf = &bl[j >> 1][(j & 1) * 2];
                    mma_bf16(acc[i][j], ah[i], bhf);
                    mma_bf16(acc[i][j], ah[i], blf);
                    mma_bf16(acc[i][j], al[i], bhf);
                }
        }
        __syncthreads();
    }

    int mrow = l >> 2, ncol = (l & 3) * 2;
#pragma unroll
    for (int i = 0; i < 4; i++) {
        int m = m0 + wm * 64 + i * 16 + mrow;
        float bv0 = bias[m], bv8 = bias[m + 8];
        float* y0 = Yb + (long)m * N;
        float* y8 = Yb + (long)(m + 8) * N;
#pragma unroll
        for (int j = 0; j < 4; j++) {
            int n = n0 + wn * 32 + j * 8 + ncol;
            if (n < N) {
                y0[n] = acc[i][j][0] + bv0;
                y8[n] = acc[i][j][2] + bv8;
            }
            if (n + 1 < N) {
                y0[n + 1] = acc[i][j][1] + bv0;
                y8[n + 1] = acc[i][j][3] + bv8;
            }
        }
    }
}

// ================= HMMA flash attention =================
// Per block: 64 q-rows, all 196 keys (padded to 208). QK and PV on tensor pipe,
// Markidis 3-term both; softmax fp32.
#define QT2 64
#define KEYP 208
#define QS2 40      // Q smem stride (32 d + 8 pad), halves
#define KS2 216     // K/V/P smem stride (208 keys + 8 pad), halves
#define SS2 212     // S stride, floats
// halves offsets
#define O_QH 0
#define O_QL 2560
#define O_KH 5120
#define O_KL 12032
#define O_VH 18944
#define O_VL 25856
#define O_PH 32768
#define O_PL 46592
#define O_S  60416  // floats start here (halves index)
#define ATTN2_SMEM (O_S * 2 + QT2 * SS2 * 4)   // 120832 + 54272 = 175104 B

__global__ __launch_bounds__(256) void attn_mma_k(
    const float* __restrict__ q, const float* __restrict__ kv, float* __restrict__ gf)
{
    extern __shared__ __align__(16) uint16_t sm2[];
    uint16_t* QH = sm2 + O_QH;  uint16_t* QL = sm2 + O_QL;
    uint16_t* KH = sm2 + O_KH;  uint16_t* KL = sm2 + O_KL;
    uint16_t* VH = sm2 + O_VH;  uint16_t* VL = sm2 + O_VL;
    uint16_t* PH = sm2 + O_PH;  uint16_t* PL = sm2 + O_PL;
    float*    S  = (float*)(sm2 + O_S);

    const uint32_t uQH = smem_u32(QH), uQL = smem_u32(QL);
    const uint32_t uKH = smem_u32(KH), uKL = smem_u32(KL);
    const uint32_t uVH = smem_u32(VH), uVL = smem_u32(VL);
    const uint32_t uPH = smem_u32(PH), uPL = smem_u32(PL);

    int bh = blockIdx.y;
    int b = bh >> 3, h = bh & 7;
    int s0 = blockIdx.x * QT2;                    // HW = 49*64 exactly
    const float* qb = q  + ((long)b * DIMC + h * DH) * HW;
    const float* kb = kv + ((long)b * 2 * DIMC + h * DH) * SP;
    const float* vb = kb + (long)DIMC * SP;
    float* gfb = gf + ((long)b * DIMC + h * DH) * HW;

    int t = threadIdx.x, w = t >> 5, l = t & 31;

    // ---- load Q transposed [s][d], scaled; K,V d-major [d][key], pad to 208 ----
    {
        int d = t >> 3;
        int sb = (t & 7) * 8;
#pragma unroll
        for (int u = 0; u < 8; u++) {
            float v = qb[(long)d * HW + s0 + sb + u] * SCAL;
            __nv_bfloat16 hv, lv; splitv(v, hv, lv);
            QH[(sb + u) * QS2 + d] = __bfloat16_as_ushort(hv);
            QL[(sb + u) * QS2 + d] = __bfloat16_as_ushort(lv);
        }
        int kbase = (t & 7) * 26;
#pragma unroll
        for (int u = 0; u < 26; u++) {
            int key = kbase + u;
            float kvv = (key < SP) ? kb[(long)d * SP + key] : 0.f;
            float vvv = (key < SP) ? vb[(long)d * SP + key] : 0.f;
            __nv_bfloat16 hv, lv;
            splitv(kvv, hv, lv);
            KH[d * KS2 + key] = __bfloat16_as_ushort(hv);
            KL[d * KS2 + key] = __bfloat16_as_ushort(lv);
            splitv(vvv, hv, lv);
            VH[d * KS2 + key] = __bfloat16_as_ushort(hv);
            VL[d * KS2 + key] = __bfloat16_as_ushort(lv);
        }
    }
    __syncthreads();

    int a_row_l = l & 15, a_k_l = (l >> 4) * 8;
    int g = l >> 3;
    int bt_k = (g & 1) * 8 + (l & 7), bt_n = (g >> 1) * 8;        // trans-B lanes (QK)
    int bn_n = (g >> 1) * 8 + (l & 7), bn_k = (g & 1) * 8;        // non-trans-B lanes (PV)
    int mrow = l >> 2, ncol = (l & 3) * 2;

    // ---- QK: S[s][key] via HMMA ----
    {
        int wm = w & 3, wn = w >> 2;
        uint32_t ah[2][4], al[2][4];
#pragma unroll
        for (int ks = 0; ks < 2; ks++) {
            uint32_t off = (uint32_t)(((wm * 16 + a_row_l) * QS2 + ks * 16 + a_k_l) * 2);
            LDSM_X4(ah[ks][0], ah[ks][1], ah[ks][2], ah[ks][3], uQH + off);
            LDSM_X4(al[ks][0], al[ks][1], al[ks][2], al[ks][3], uQL + off);
        }
#pragma unroll 1
        for (int c = wn; c < 13; c += 2) {
            uint32_t bh0[2][4], bl0[2][4];
#pragma unroll
            for (int ks = 0; ks < 2; ks++) {
                uint32_t off = (uint32_t)(((ks * 16 + bt_k) * KS2 + c * 16 + bt_n) * 2);
                LDSM_X4_T(bh0[ks][0], bh0[ks][1], bh0[ks][2], bh0[ks][3], uKH + off);
                LDSM_X4_T(bl0[ks][0], bl0[ks][1], bl0[ks][2], bl0[ks][3], uKL + off);
            }
            float acc[2][4];
#pragma unroll
            for (int j = 0; j < 2; j++)
#pragma unroll
                for (int r = 0; r < 4; r++) acc[j][r] = 0.f;
#pragma unroll
            for (int ks = 0; ks < 2; ks++)
#pragma unroll
                for (int j = 0; j < 2; j++) {
                    const uint32_t* bhf = &bh0[ks][j * 2];
                    const uint32_t* blf = &bl0[ks][j * 2];
                    mma_bf16(acc[j], ah[ks], bhf);
                    mma_bf16(acc[j], ah[ks], blf);
                    mma_bf16(acc[j], al[ks], bhf);
                }
#pragma unroll
            for (int j = 0; j < 2; j++) {
                int key = c * 16 + j * 8 + ncol;
                S[(wm * 16 + mrow) * SS2 + key] = acc[j][0];
                S[(wm * 16 + mrow) * SS2 + key + 1] = acc[j][1];
                S[(wm * 16 + mrow + 8) * SS2 + key] = acc[j][2];
                S[(wm * 16 + mrow + 8) * SS2 + key + 1] = acc[j][3];
            }
        }
    }
    __syncthreads();

    // ---- softmax (fp32), emit P bf16 hi/lo, zero pad cols ----
    {
        for (int rr = 0; rr < 8; rr++) {
            int row = w * 8 + rr;
            float* srow = S + row * SS2;
            float v[7];
            float mx = -1e30f;
#pragma unroll
            for (int u = 0; u < 7; u++) {
                int idx = l + 32 * u;
                v[u] = (idx < SP) ? srow[idx] : -1e30f;
                mx = fmaxf(mx, v[u]);
            }
#pragma unroll
            for (int off = 16; off; off >>= 1) mx = fmaxf(mx, __shfl_xor_sync(0xffffffffu, mx, off));
            float s = 0.f;
#pragma unroll
            for (int u = 0; u < 7; u++) {
                int idx = l + 32 * u;
                v[u] = (idx < SP) ? __expf(v[u] - mx) : 0.f;
                s += v[u];
            }
#pragma unroll
            for (int off = 16; off; off >>= 1) s += __shfl_xor_sync(0xffffffffu, s, off);
            float inv = 1.f / s;
#pragma unroll
            for (int u = 0; u < 7; u++) {
                int idx = l + 32 * u;
                if (idx < KEYP) {
                    float p = (idx < SP) ? v[u] * inv : 0.f;
                    __nv_bfloat16 hv, lv; splitv(p, hv, lv);
                    PH[row * KS2 + idx] = __bfloat16_as_ushort(hv);
                    PL[row * KS2 + idx] = __bfloat16_as_ushort(lv);
                }
            }
        }
    }
    __syncthreads();

    // ---- PV: O[s][d] via HMMA ----
    {
        int wm = w & 3, wn = w >> 2;
        float acc[2][4];
#pragma unroll
        for (int j = 0; j < 2; j++)
#pragma unroll
            for (int r = 0; r < 4; r++) acc[j][r] = 0.f;
#pragma unroll 1
        for (int kk = 0; kk < 13; kk++) {
            uint32_t ah2[4], al2[4], vh2[4], vl2[4];
            uint32_t offA = (uint32_t)(((wm * 16 + a_row_l) * KS2 + kk * 16 + a_k_l) * 2);
            LDSM_X4(ah2[0], ah2[1], ah2[2], ah2[3], uPH + offA);
            LDSM_X4(al2[0], al2[1], al2[2], al2[3], uPL + offA);
            uint32_t offB = (uint32_t)(((wn * 16 + bn_n) * KS2 + kk * 16 + bn_k) * 2);
            LDSM_X4(vh2[0], vh2[1], vh2[2], vh2[3], uVH + offB);
            LDSM_X4(vl2[0], vl2[1], vl2[2], vl2[3], uVL + offB);
#pragma unroll
            for (int j = 0; j < 2; j++) {
                const uint32_t* bhf = &vh2[j * 2];
                const uint32_t* blf = &vl2[j * 2];
                mma_bf16(acc[j], ah2, bhf);
                mma_bf16(acc[j], al2, bhf);
                mma_bf16(acc[j], ah2, blf);
            }
        }
#pragma unroll
        for (int j = 0; j < 2; j++) {
            int d0 = wn * 16 + j * 8 + ncol;
            int sA = s0 + wm * 16 + mrow;
            gfb[(long)d0 * HW + sA] = acc[j][0];
            gfb[(long)(d0 + 1) * HW + sA] = acc[j][1];
            gfb[(long)d0 * HW + sA + 8] = acc[j][2];
            gfb[(long)(d0 + 1) * HW + sA + 8] = acc[j][3];
        }
    }
}

// ================= depthwise 5x5 + BN, bf16 hi/lo output =================
__global__ void dwconv_bn_k(
    const float* __restrict__ x, const float* __restrict__ w, const float* __restrict__ cb,
    const float* __restrict__ bng, const float* __restrict__ bnb,
    const float* __restrict__ bnm, const float* __restrict__ bnv,
    __nv_bfloat16* __restrict__ yh, __nv_bfloat16* __restrict__ yl,
    int Hin, int Win, int Hout, int Wout, int stride)
{
    long idx = (long)blockIdx.x * blockDim.x + threadIdx.x;
    long total = (long)BATCH * DIMC * Hout * Wout;
    if (idx >= total) return;
    int ow = idx % Wout;
    long r = idx / Wout;
    int oh = r % Hout; r /= Hout;
    int c = r % DIMC;
    long bc = idx / ((long)Hout * Wout);
    const float* xp = x + bc * Hin * Win;
    const float* wp = w + c * 25;
    float acc = cb[c];
    int ih0 = oh * stride - 2, iw0 = ow * stride - 2;
#pragma unroll
    for (int kh = 0; kh < 5; kh++) {
        int ih = ih0 + kh;
        if (ih < 0 || ih >= Hin) continue;
#pragma unroll
        for (int kw = 0; kw < 5; kw++) {
            int iw = iw0 + kw;
            if (iw < 0 || iw >= Win) continue;
            acc += xp[ih * Win + iw] * wp[kh * 5 + kw];
        }
    }
    float sc = bng[c] * rsqrtf(bnv[c] + 1e-5f);
    acc = (acc - bnm[c]) * sc + bnb[c];
    __nv_bfloat16 hv, lv;
    splitv(acc, hv, lv);
    yh[idx] = hv; yl[idx] = lv;
}

// ================= local mixer + gating, bf16 hi/lo output =================
__global__ void gate_k(
    const float* __restrict__ qloc, const float* __restrict__ gf,
    const float* __restrict__ lw, const float* __restrict__ lb,
    __nv_bfloat16* __restrict__ oh2, __nv_bfloat16* __restrict__ ol2)
{
    long idx = (long)blockIdx.x * blockDim.x + threadIdx.x;
    if (idx >= (long)BATCH * DIMC * HW) return;
    int s = idx % HW;
    int c = (idx / HW) % DIMC;
    int ow = s % WW, oh = s / WW;
    const float* xp = qloc + (idx / HW) * HW;
    const float* wp = lw + c * 25;
    float acc = lb[c];
#pragma unroll
    for (int kh = 0; kh < 5; kh++) {
        int ih = oh - 2 + kh;
        if (ih < 0 || ih >= HH) continue;
#pragma unroll
        for (int kw = 0; kw < 5; kw++) {
            int iw = ow - 2 + kw;
            if (iw < 0 || iw >= WW) continue;
            acc += xp[ih * WW + iw] * wp[kh * 5 + kw];
        }
    }
    float l = acc;
    float lf = l * (1.f / (1.f + __expf(-l)));
    float g = gf[idx];
    float gated = lf * (1.f / (1.f + __expf(-g)));
    float v = gated * g;
    __nv_bfloat16 hv, lv;
    splitv(v, hv, lv);
    oh2[idx] = hv; ol2[idx] = lv;
}

// ================= host =================
static inline int cdiv(int a, int b) { return (a + b - 1) / b; }

extern "C" void kernel_launch(void* const* d_in, const int* in_sizes, int n_in,
                              void* d_out, int out_size)
{
    const float* x     = (const float*)d_in[0];
    const float* q_w   = (const float*)d_in[1];
    const float* q_b   = (const float*)d_in[2];
    const float* kv_w  = (const float*)d_in[3];
    const float* kv_b  = (const float*)d_in[4];
    const float* p0_w  = (const float*)d_in[5];
    const float* p0_b  = (const float*)d_in[6];
    const float* bn0_g = (const float*)d_in[7];
    const float* bn0_b = (const float*)d_in[8];
    const float* bn0_m = (const float*)d_in[9];
    const float* bn0_v = (const float*)d_in[10];
    const float* pl0_w = (const float*)d_in[11];
    const float* pl0_b = (const float*)d_in[12];
    const float* p1_w  = (const float*)d_in[13];
    const float* p1_b  = (const float*)d_in[14];
    const float* bn1_g = (const float*)d_in[15];
    const float* bn1_b = (const float*)d_in[16];
    const float* bn1_m = (const float*)d_in[17];
    const float* bn1_v = (const float*)d_in[18];
    const float* loc_w = (const float*)d_in[19];
    const float* loc_b = (const float*)d_in[20];
    const float* mix_w = (const float*)d_in[21];
    const float* mix_b = (const float*)d_in[22];
    float* out = (float*)d_out;

    float *q, *p28b, *kv, *gf;
    cudaGetSymbolAddress((void**)&q,    g_q);
    cudaGetSymbolAddress((void**)&p28b, g_p28b);
    cudaGetSymbolAddress((void**)&kv,   g_kv);
    cudaGetSymbolAddress((void**)&gf,   g_gf);

    __nv_bfloat16 *xh, *xl, *p28h, *p28l, *p14h, *p14l, *mixh, *mixl;
    __nv_bfloat16 *wqh, *wql, *wph, *wpl, *wkh, *wkl, *wmh, *wml;
    cudaGetSymbolAddress((void**)&xh, g_xh);     cudaGetSymbolAddress((void**)&xl, g_xl);
    cudaGetSymbolAddress((void**)&p28h, g_p28h); cudaGetSymbolAddress((void**)&p28l, g_p28l);
    cudaGetSymbolAddress((void**)&p14h, g_p14h); cudaGetSymbolAddress((void**)&p14l, g_p14l);
    cudaGetSymbolAddress((void**)&mixh, g_mixh); cudaGetSymbolAddress((void**)&mixl, g_mixl);
    cudaGetSymbolAddress((void**)&wqh, g_wqh);   cudaGetSymbolAddress((void**)&wql, g_wql);
    cudaGetSymbolAddress((void**)&wph, g_wph);   cudaGetSymbolAddress((void**)&wpl, g_wpl);
    cudaGetSymbolAddress((void**)&wkh, g_wkh);   cudaGetSymbolAddress((void**)&wkl, g_wkl);
    cudaGetSymbolAddress((void**)&wmh, g_wmh);   cudaGetSymbolAddress((void**)&wml, g_wml);

    cudaFuncSetAttribute(attn_mma_k, cudaFuncAttributeMaxDynamicSharedMemorySize, (int)ATTN2_SMEM);

    dim3 tb(256);

    // 0) pre-split GEMM inputs
    {
        long nx = (long)BATCH * DIMC * HW;
        split_k<<<(int)((nx + 255) / 256), tb>>>(x, xh, xl, nx);
        split_k<<<(DIMC * DIMC + 255) / 256, tb>>>(q_w, wqh, wql, DIMC * DIMC);
        split_k<<<(DIMC * DIMC + 255) / 256, tb>>>(pl0_w, wph, wpl, DIMC * DIMC);
        split_k<<<(2 * DIMC * DIMC + 255) / 256, tb>>>(kv_w, wkh, wkl, 2 * DIMC * DIMC);
        split_k<<<(DIMC * DIMC + 255) / 256, tb>>>(mix_w, wmh, wml, DIMC * DIMC);
    }

    // 1) q_local = 1x1 conv
    conv_mma2_k<<<dim3(cdiv(HW, 128), DIMC / 128, BATCH), tb>>>(wqh, wql, xh, xl, q_b, q, DIMC, HW);

    // 2) p0 dwconv s2 + BN0 (56->28), bf16 out
    dwconv_bn_k<<<cdiv(BATCH * DIMC * S28, 256), tb>>>(
        x, p0_w, p0_b, bn0_g, bn0_b, bn0_m, bn0_v, p28h, p28l, HH, WW, H28, H28, 2);

    // 3) pl0 1x1 conv (fp32 out)
    conv_mma2_k<<<dim3(cdiv(S28, 128), DIMC / 128, BATCH), tb>>>(wph, wpl, p28h, p28l, pl0_b, p28b, DIMC, S28);

    // 4) p1 dwconv s2 + BN1 (28->14), bf16 out
    dwconv_bn_k<<<cdiv(BATCH * DIMC * SP, 256), tb>>>(
        p28b, p1_w, p1_b, bn1_g, bn1_b, bn1_m, bn1_v, p14h, p14l, H28, H28, HP, HP, 2);

    // 5) kv 1x1 conv (M=512)
    conv_mma2_k<<<dim3(cdiv(SP, 128), 2 * DIMC / 128, BATCH), tb>>>(wkh, wkl, p14h, p14l, kv_b, kv, 2 * DIMC, SP);

    // 6) fused attention (HMMA)
    attn_mma_k<<<dim3(HW / QT2, BATCH * HEADS), tb, ATTN2_SMEM>>>(q, kv, gf);

    // 7) local mixer + gating, bf16 out
    gate_k<<<cdiv(BATCH * DIMC * HW, 256), tb>>>(q, gf, loc_w, loc_b, mixh, mixl);

    // 8) mix 1x1 conv -> out
    conv_mma2_k<<<dim3(cdiv(HW, 128), DIMC / 128, BATCH), tb>>>(wmh, wml, mixh, mixl, mix_b, out, DIMC, HW);
}